// round 5
// baseline (speedup 1.0000x reference)
#include <cuda_runtime.h>

#define NN 8192
#define CC 128
#define NF4 2048
#define FULLMASK 0xFFFFFFFFu
#define CAP 128
#define BM 64

// ---- scratch ----
__device__ float g_h[NN * CC];
__device__ float g_hx[NN * CC];        // dense-half partial (X @ Wc^T)
__device__ int   g_degi[NN];
__device__ int   g_cnt[NN];
__device__ int   g_bkt[NN * CAP];
__device__ float g_BT[2 * CC * CC];    // [Wn^T ; Wc^T], K-major [256][128]
__device__ float g_sum[CC];
__device__ float g_sumsq[CC];

__device__ __forceinline__ void ffma2(unsigned long long& d, unsigned long long a, unsigned long long b) {
    asm("fma.rn.f32x2 %0, %1, %2, %0;" : "+l"(d) : "l"(a), "l"(b));
}
__device__ __forceinline__ unsigned long long pack2(float x) {
    unsigned long long r; asm("mov.b64 %0, {%1, %1};" : "=l"(r) : "f"(x)); return r;
}

// ---------------------------------------------------------------
// zero counters & BN accumulators (runs on s2 before the scan)
__global__ void k_zero() {
    int idx = blockIdx.x * 256 + threadIdx.x;     // 16 blocks * 256 = 4096
#pragma unroll
    for (int r = 0; r < 2; ++r) {
        int i = idx * 2 + r;
        if (i < NN) { g_degi[i] = 0; g_cnt[i] = 0; }
    }
    if (idx < CC) { g_sum[idx] = 0.f; g_sumsq[idx] = 0.f; }
}

// ---------------------------------------------------------------
// transpose Wn,Wc into g_BT (runs on main stream)
__global__ void k_prep(const float* __restrict__ Wn, const float* __restrict__ Wc) {
    __shared__ float s[32][33];
    int bid = blockIdx.x;                 // 32 blocks
    int m = bid >> 4;
    int t = bid & 15;
    int tr = (t >> 2) * 32;
    int tc = (t & 3) * 32;
    const float* src = m ? Wc : Wn;
    float* dst = g_BT + m * CC * CC;
    int x = threadIdx.x & 31;
    int y0 = threadIdx.x >> 5;
#pragma unroll
    for (int dy = 0; dy < 32; dy += 8)
        s[y0 + dy][x] = src[(tr + y0 + dy) * CC + tc + x];
    __syncthreads();
#pragma unroll
    for (int dy = 0; dy < 32; dy += 8)
        dst[(tc + y0 + dy) * CC + tr + x] = s[x][y0 + dy];
}

// ---------------------------------------------------------------
__global__ void k_scan(const float4* __restrict__ A4) {
    const int lane = threadIdx.x & 31;
    const long stride = (long)gridDim.x * blockDim.x;
    const long total = (long)NN * NF4;

    for (long q0 = (long)blockIdx.x * blockDim.x + threadIdx.x; q0 < total; q0 += 4 * stride) {
        float4 v[4];
#pragma unroll
        for (int u = 0; u < 4; ++u) v[u] = __ldcs(&A4[q0 + (long)u * stride]);
#pragma unroll
        for (int u = 0; u < 4; ++u) {
            long qu = q0 + (long)u * stride;
            int e0 = v[u].x != 0.f, e1 = v[u].y != 0.f;
            int e2 = v[u].z != 0.f, e3 = v[u].w != 0.f;
            int cnt = e0 + e1 + e2 + e3;
            unsigned anyb = __ballot_sync(FULLMASK, cnt);
            if (!anyb) continue;
            int j = (int)(qu >> 11);
            int tot = __reduce_add_sync(FULLMASK, cnt);
            if (lane == 0) atomicAdd(&g_degi[j], tot);
            if (cnt) {
                int cbase = (int)(qu & 2047) * 4;
                float vv[4] = {v[u].x, v[u].y, v[u].z, v[u].w};
#pragma unroll
                for (int s = 0; s < 4; ++s) {
                    if (vv[s] != 0.f) {
                        int i = cbase + s;
                        int pos = atomicAdd(&g_cnt[i], 1);
                        if (pos < CAP) g_bkt[i * CAP + pos] = j;
                    }
                }
            }
        }
    }
}

// ---------------------------------------------------------------
// Dense half: g_hx = X @ Wc^T   (no dependence on the scan)
__global__ void __launch_bounds__(512, 1)
k_gemmX(const float* __restrict__ X) {
    extern __shared__ float sh[];
    float* Bs = sh;                 // WcT: 16384 floats (64KB)
    float* As = sh + CC * CC;       // X tile: 8192 floats (32KB)

    const int tid = threadIdx.x;
    const int m0  = blockIdx.x * BM;

    {
        const float4* src = (const float4*)(g_BT + CC * CC);
        float4* dst = (float4*)Bs;
#pragma unroll
        for (int i = 0; i < 8; ++i) dst[tid + i * 512] = src[tid + i * 512];
        const float4* xs = (const float4*)(X + (size_t)m0 * CC);
        float4* ad = (float4*)As;
#pragma unroll
        for (int i = 0; i < 4; ++i) ad[tid + i * 512] = __ldg(xs + tid + i * 512);
    }
    __syncthreads();

    const int cg = tid & 63;
    const int rg = tid >> 6;
    unsigned long long acc[8];
#pragma unroll
    for (int r = 0; r < 8; ++r) acc[r] = 0ull;

    const float* bb = Bs + cg * 2;
    const float* ab = As + rg * 8 * CC;
#pragma unroll 2
    for (int kk = 0; kk < CC; kk += 4) {
        float4 a[8];
#pragma unroll
        for (int r = 0; r < 8; ++r) a[r] = *(const float4*)(ab + r * CC + kk);
#pragma unroll
        for (int j = 0; j < 4; ++j) {
            unsigned long long bp = *(const unsigned long long*)(bb + (kk + j) * CC);
            float av[8];
#pragma unroll
            for (int r = 0; r < 8; ++r)
                av[r] = (j == 0) ? a[r].x : (j == 1) ? a[r].y : (j == 2) ? a[r].z : a[r].w;
#pragma unroll
            for (int r = 0; r < 8; ++r)
                ffma2(acc[r], pack2(av[r]), bp);
        }
    }
#pragma unroll
    for (int r = 0; r < 8; ++r) {
        int m = m0 + rg * 8 + r;
        *(float2*)(g_hx + (size_t)m * CC + cg * 2) = *(float2*)&acc[r];
    }
}

// ---------------------------------------------------------------
// Sparse half: gather agg, acc = agg @ Wn^T, h = acc + hx + bias; BN stats.
__global__ void __launch_bounds__(512, 1)
k_gemmA(const float* __restrict__ X, const float* __restrict__ bn, const float* __restrict__ bc) {
    extern __shared__ float sh[];
    float* Bs = sh;                 // WnT: 16384 floats
    float* As = sh + CC * CC;       // agg tile: 8192 floats

    const int tid  = threadIdx.x;
    const int lane = tid & 31;
    const int wid  = tid >> 5;
    const int m0   = blockIdx.x * BM;

    {
        const float4* src = (const float4*)g_BT;
        float4* dst = (float4*)Bs;
#pragma unroll
        for (int i = 0; i < 8; ++i) dst[tid + i * 512] = src[tid + i * 512];
    }

    const float4* X4 = (const float4*)X;
#pragma unroll 1
    for (int r = 0; r < 4; ++r) {
        int row  = wid * 4 + r;
        int node = m0 + row;
        int cnt = g_cnt[node]; if (cnt > CAP) cnt = CAP;
        int dg  = g_degi[node];
        float rdeg = (dg > 0) ? (1.f / (float)dg) : 1.f;
        const int* bk = g_bkt + node * CAP;
        int nb[4];
#pragma unroll
        for (int w = 0; w < 4; ++w) nb[w] = (lane + 32 * w < cnt) ? bk[lane + 32 * w] : 0;

        float4 acc = {0.f, 0.f, 0.f, 0.f};
        int t = 0;
        for (; t + 4 <= cnt; t += 4) {
            int j0 = __shfl_sync(FULLMASK, nb[(t + 0) >> 5], (t + 0) & 31);
            int j1 = __shfl_sync(FULLMASK, nb[(t + 1) >> 5], (t + 1) & 31);
            int j2 = __shfl_sync(FULLMASK, nb[(t + 2) >> 5], (t + 2) & 31);
            int j3 = __shfl_sync(FULLMASK, nb[(t + 3) >> 5], (t + 3) & 31);
            float4 x0 = __ldg(X4 + (long)j0 * 32 + lane);
            float4 x1 = __ldg(X4 + (long)j1 * 32 + lane);
            float4 x2 = __ldg(X4 + (long)j2 * 32 + lane);
            float4 x3 = __ldg(X4 + (long)j3 * 32 + lane);
            acc.x += x0.x + x1.x + x2.x + x3.x;
            acc.y += x0.y + x1.y + x2.y + x3.y;
            acc.z += x0.z + x1.z + x2.z + x3.z;
            acc.w += x0.w + x1.w + x2.w + x3.w;
        }
        for (; t < cnt; ++t) {
            int j = __shfl_sync(FULLMASK, nb[t >> 5], t & 31);
            float4 x = __ldg(X4 + (long)j * 32 + lane);
            acc.x += x.x; acc.y += x.y; acc.z += x.z; acc.w += x.w;
        }
        acc.x *= rdeg; acc.y *= rdeg; acc.z *= rdeg; acc.w *= rdeg;
        *(float4*)(As + (size_t)row * CC + lane * 4) = acc;
    }
    __syncthreads();

    const int cg = tid & 63;
    const int rg = tid >> 6;
    unsigned long long acc[8];
#pragma unroll
    for (int r = 0; r < 8; ++r) acc[r] = 0ull;

    const float* bb = Bs + cg * 2;
    const float* ab = As + rg * 8 * CC;
#pragma unroll 2
    for (int kk = 0; kk < CC; kk += 4) {
        float4 a[8];
#pragma unroll
        for (int r = 0; r < 8; ++r) a[r] = *(const float4*)(ab + r * CC + kk);
#pragma unroll
        for (int j = 0; j < 4; ++j) {
            unsigned long long bp = *(const unsigned long long*)(bb + (kk + j) * CC);
            float av[8];
#pragma unroll
            for (int r = 0; r < 8; ++r)
                av[r] = (j == 0) ? a[r].x : (j == 1) ? a[r].y : (j == 2) ? a[r].z : a[r].w;
#pragma unroll
            for (int r = 0; r < 8; ++r)
                ffma2(acc[r], pack2(av[r]), bp);
        }
    }

    // ---- epilogue: combine, bias, stats ----
    __syncthreads();
    float* s_sum = sh;
    float* s_sq  = sh + CC;
    if (tid < CC) { s_sum[tid] = 0.f; s_sq[tid] = 0.f; }
    __syncthreads();

    float b0 = bn[cg * 2] + bc[cg * 2];
    float b1 = bn[cg * 2 + 1] + bc[cg * 2 + 1];

    float ps0 = 0.f, ps1 = 0.f, pq0 = 0.f, pq1 = 0.f;
#pragma unroll
    for (int r = 0; r < 8; ++r) {
        int m = m0 + rg * 8 + r;
        float2 p  = *(float2*)&acc[r];
        float2 hx = *(const float2*)(g_hx + (size_t)m * CC + cg * 2);
        float h0 = p.x + hx.x + b0, h1 = p.y + hx.y + b1;
        ps0 += h0; ps1 += h1;
        pq0 += h0 * h0; pq1 += h1 * h1;
        float2 hv = {h0, h1};
        *(float2*)(g_h + (size_t)m * CC + cg * 2) = hv;
    }
    atomicAdd(&s_sum[cg * 2], ps0);
    atomicAdd(&s_sum[cg * 2 + 1], ps1);
    atomicAdd(&s_sq[cg * 2], pq0);
    atomicAdd(&s_sq[cg * 2 + 1], pq1);
    __syncthreads();
    if (tid < CC) {
        atomicAdd(&g_sum[tid],   s_sum[tid]);
        atomicAdd(&g_sumsq[tid], s_sq[tid]);
    }
}

// ---------------------------------------------------------------
__global__ void k_norm(const float* __restrict__ gamma, const float* __restrict__ beta,
                       float* __restrict__ out) {
    const int tid = blockIdx.x * blockDim.x + threadIdx.x;   // 131072 threads
    const int c0 = (tid & 31) * 4;
    const float invN = 1.f / (float)NN;
    float scale[4], shift[4];
#pragma unroll
    for (int i = 0; i < 4; ++i) {
        int c = c0 + i;
        float mu  = g_sum[c] * invN;
        float var = fmaxf(g_sumsq[c] * invN - mu * mu, 0.f);
        float inv = rsqrtf(var + 1e-5f);
        float sc = __ldg(gamma + c) * inv;
        scale[i] = sc;
        shift[i] = __ldg(beta + c) - mu * sc;
    }
    const float4* hp = (const float4*)g_h;
    float4* op = (float4*)out;
#pragma unroll
    for (int u = 0; u < 2; ++u) {
        int idx = tid + u * 131072;
        float4 h = __ldcs(hp + idx);
        float4 o;
        o.x = fmaxf(fmaf(h.x, scale[0], shift[0]), 0.f);
        o.y = fmaxf(fmaf(h.y, scale[1], shift[1]), 0.f);
        o.z = fmaxf(fmaf(h.z, scale[2], shift[2]), 0.f);
        o.w = fmaxf(fmaf(h.w, scale[3], shift[3]), 0.f);
        op[idx] = o;
    }
}

// ---------------------------------------------------------------
extern "C" void kernel_launch(void* const* d_in, const int* in_sizes, int n_in,
                              void* d_out, int out_size) {
    const float* Xf    = (const float*)d_in[0];
    const float* A     = (const float*)d_in[1];
    const float* Wn    = (const float*)d_in[2];
    const float* bn    = (const float*)d_in[3];
    const float* Wc    = (const float*)d_in[4];
    const float* bc    = (const float*)d_in[5];
    const float* gamma = (const float*)d_in[6];
    const float* beta  = (const float*)d_in[7];
    if (in_sizes[0] > in_sizes[1]) { const float* t = Xf; Xf = A; A = t; }

    float* out = (float*)d_out;

    // one-time aux resources (created on the un-captured correctness call)
    static cudaStream_t s2 = []() {
        cudaStream_t s; cudaStreamCreateWithFlags(&s, cudaStreamNonBlocking); return s;
    }();
    static cudaEvent_t evF = []() {
        cudaEvent_t e; cudaEventCreateWithFlags(&e, cudaEventDisableTiming); return e;
    }();
    static cudaEvent_t evJ = []() {
        cudaEvent_t e; cudaEventCreateWithFlags(&e, cudaEventDisableTiming); return e;
    }();
    static bool attr_done = []() {
        size_t smem = (size_t)(CC * CC + BM * CC) * sizeof(float);   // 96KB
        cudaFuncSetAttribute(k_gemmX, cudaFuncAttributeMaxDynamicSharedMemorySize, (int)smem);
        cudaFuncSetAttribute(k_gemmA, cudaFuncAttributeMaxDynamicSharedMemorySize, (int)smem);
        return true;
    }();
    (void)attr_done;

    const size_t smem = (size_t)(CC * CC + BM * CC) * sizeof(float);

    // fork: scan path on s2
    cudaEventRecord(evF, 0);
    cudaStreamWaitEvent(s2, evF, 0);
    k_zero<<<16, 256, 0, s2>>>();
    k_scan<<<2048, 256, 0, s2>>>((const float4*)A);
    cudaEventRecord(evJ, s2);

    // main stream: weight transpose + dense half (overlaps the scan)
    k_prep<<<32, 256>>>(Wn, Wc);
    k_gemmX<<<NN / BM, 512, smem>>>(Xf);

    // join, then sparse half + norm
    cudaStreamWaitEvent(0, evJ, 0);
    k_gemmA<<<NN / BM, 512, smem>>>(Xf, bn, bc);
    k_norm<<<512, 256>>>(gamma, beta, out);
}